// round 3
// baseline (speedup 1.0000x reference)
#include <cuda_runtime.h>
#include <math.h>
#include <stdint.h>

static constexpr int kN  = 384;
static constexpr int kD  = 256;
static constexpr int kH  = 8;
static constexpr int kDH = 32;
static constexpr float kScale = 0.17677669529663687f;  // 1/sqrt(32)
static constexpr int kERow = kN * kD;                  // 98304 floats per e row i

// ---------------- scratch (__device__ globals; no allocation) ----------------
__device__ float qx_g[kN * kD];
__device__ float kx_g[kN * kD];
__device__ float vx_g[kN * kD];
__device__ float cen_g[kN * kH];      // qx . bk_e   (per i,h)
__device__ float cne_g[kN * kH];      // kx . bq_e   (per n,h)
__device__ float u_g[kN * kH * kD];   // [i][h][d]  Wk_e_h @ qx[h,i]
__device__ float w_g[kN * kH * kD];   // [n][h][d]  Wq_e_h @ kx[h,n]
__device__ float P_g[kN * kH * kD];   // [n][h][d]  vx_h[n] @ WOe rows h
__device__ float g_g[kN * kH * kD];   // [i][h][d]  sum_j a_en * e[i,j,:]

// ---------------- K1: qx/kx/vx projections + score constants ----------------
__global__ __launch_bounds__(256) void k1_proj(
    const float* __restrict__ x,
    const float* __restrict__ Wq, const float* __restrict__ bq,
    const float* __restrict__ Wk, const float* __restrict__ bk,
    const float* __restrict__ Wv, const float* __restrict__ bv,
    const float* __restrict__ bk_e, const float* __restrict__ bq_e)
{
    __shared__ float xs[kD];
    int i = blockIdx.x, c = threadIdx.x;
    xs[c] = x[i * kD + c];
    __syncthreads();
    int h = c >> 5, k = c & 31;
    const float* wq = Wq + h * 8192 + k;   // W[h,d,k] = W[h*8192 + d*32 + k]
    const float* wk = Wk + h * 8192 + k;
    const float* wv = Wv + h * 8192 + k;
    float q = 0.f, kk = 0.f, v = 0.f;
#pragma unroll 8
    for (int d = 0; d < kD; d++) {
        float xv = xs[d];
        q  = fmaf(xv, wq[d * 32], q);
        kk = fmaf(xv, wk[d * 32], kk);
        v  = fmaf(xv, wv[d * 32], v);
    }
    q += bq[c]; kk += bk[c]; v += bv[c];
    qx_g[i * kD + c] = q;
    kx_g[i * kD + c] = kk;
    vx_g[i * kD + c] = v;

    // cen[i,h] = sum_k bk_e[h,k]*qx[h,i,k];  cne[i,h] = sum_k bq_e[h,k]*kx[h,i,k]
    float ce = bk_e[c] * q;
    float cn = bq_e[c] * kk;
#pragma unroll
    for (int o = 16; o; o >>= 1) {
        ce += __shfl_xor_sync(0xffffffffu, ce, o);
        cn += __shfl_xor_sync(0xffffffffu, cn, o);
    }
    if (k == 0) { cen_g[i * kH + h] = ce; cne_g[i * kH + h] = cn; }
}

// ---------------- K1b: u / w / P tables (weights in registers, reuse x16) ----
__global__ __launch_bounds__(256) void k1b_uwp(
    const float* __restrict__ Wk_e,
    const float* __restrict__ Wq_e,
    const float* __restrict__ WOe)
{
    __shared__ float qs[16 * 32], ks[16 * 32], vs[16 * 32];
    int ib = blockIdx.x, h = blockIdx.y;
    int d = threadIdx.x;
    for (int idx = threadIdx.x; idx < 512; idx += 256) {
        int ii = idx >> 5, k = idx & 31;
        int g = (ib * 16 + ii) * kD + h * 32 + k;
        qs[idx] = qx_g[g]; ks[idx] = kx_g[g]; vs[idx] = vx_g[g];
    }
    __syncthreads();

    float wr[32];
#pragma unroll
    for (int k = 0; k < 32; k++) wr[k] = Wk_e[h * 8192 + d * 32 + k];
    for (int ii = 0; ii < 16; ii++) {
        float a = 0.f;
#pragma unroll
        for (int k = 0; k < 32; k++) a = fmaf(wr[k], qs[ii * 32 + k], a);
        u_g[((ib * 16 + ii) * kH + h) * kD + d] = a;
    }
#pragma unroll
    for (int k = 0; k < 32; k++) wr[k] = Wq_e[h * 8192 + d * 32 + k];
    for (int ii = 0; ii < 16; ii++) {
        float a = 0.f;
#pragma unroll
        for (int k = 0; k < 32; k++) a = fmaf(wr[k], ks[ii * 32 + k], a);
        w_g[((ib * 16 + ii) * kH + h) * kD + d] = a;
    }
#pragma unroll
    for (int k = 0; k < 32; k++) wr[k] = WOe[(h * 32 + k) * kD + d];
    for (int ii = 0; ii < 16; ii++) {
        float a = 0.f;
#pragma unroll
        for (int k = 0; k < 32; k++) a = fmaf(wr[k], vs[ii * 32 + k], a);
        P_g[((ib * 16 + ii) * kH + h) * kD + d] = a;
    }
}

// ---------------- K2: edge->node attention (scores, softmax, g) --------------
// smem layout (floats): u_s 8*260 | s_s 8*388 | e_s 32*260   = 13504 fl = 54016 B
static constexpr int K2_SMEM = (8 * 260 + 8 * 388 + 32 * 260) * 4;

__device__ __forceinline__ void k2_load_etile(float* e_s, const float* erow, int j0)
{
    const float4* src = (const float4*)(erow + j0 * kD);
    int t = threadIdx.x;
#pragma unroll
    for (int r = 0; r < 8; r++) {
        int idx = t + r * 256;           // float4 index, 0..2047
        int row = idx >> 6, dd = idx & 63;
        float4 v = src[idx];
        *(float4*)(e_s + row * 260 + dd * 4) = v;
    }
}

__global__ __launch_bounds__(256) void k2_en(const float* __restrict__ e)
{
    extern __shared__ float sm[];
    float* u_s = sm;            // 8*260
    float* s_s = sm + 2080;     // 8*388
    float* e_s = sm + 5184;     // 32*260
    __shared__ float cen_s[8];

    int i = blockIdx.x, t = threadIdx.x;
#pragma unroll
    for (int r = 0; r < 8; r++) {
        int idx = t + r * 256;
        int h = idx >> 8, d = idx & 255;
        u_s[h * 260 + d] = u_g[(i * kH + h) * kD + d];
    }
    if (t < 8) cen_s[t] = cen_g[i * kH + t];
    const float* erow = e + (size_t)i * kERow;

    int h = t & 7, jj = t >> 3;
    // pass A: scores for all j (s_s[h][j])
    for (int j0 = 0; j0 < kN; j0 += 32) {
        __syncthreads();
        k2_load_etile(e_s, erow, j0);
        __syncthreads();
        const float4* ev = (const float4*)(e_s + jj * 260);
        const float4* uv = (const float4*)(u_s + h * 260);
        float acc = 0.f;
#pragma unroll 16
        for (int d4 = 0; d4 < 64; d4++) {
            float4 a = ev[d4], b = uv[d4];
            acc = fmaf(a.x, b.x, acc); acc = fmaf(a.y, b.y, acc);
            acc = fmaf(a.z, b.z, acc); acc = fmaf(a.w, b.w, acc);
        }
        s_s[h * 388 + j0 + jj] = (acc + cen_s[h]) * kScale;
    }
    __syncthreads();

    // softmax per head, one warp per h
    {
        int hw = t >> 5, l = t & 31;
        float m = -1e30f;
        for (int j = l; j < kN; j += 32) m = fmaxf(m, s_s[hw * 388 + j]);
#pragma unroll
        for (int o = 16; o; o >>= 1) m = fmaxf(m, __shfl_xor_sync(0xffffffffu, m, o));
        float sum = 0.f;
        for (int j = l; j < kN; j += 32) {
            float ev = __expf(s_s[hw * 388 + j] - m);
            s_s[hw * 388 + j] = ev;
            sum += ev;
        }
#pragma unroll
        for (int o = 16; o; o >>= 1) sum += __shfl_xor_sync(0xffffffffu, sum, o);
        float inv = 1.f / sum;
        for (int j = l; j < kN; j += 32) s_s[hw * 388 + j] *= inv;
    }
    __syncthreads();

    // pass B: g[h][d] = sum_j a[h][j] * e[j][d]; thread owns column d = t
    float acc[8];
#pragma unroll
    for (int hh = 0; hh < 8; hh++) acc[hh] = 0.f;
    for (int j0 = 0; j0 < kN; j0 += 32) {
        __syncthreads();
        k2_load_etile(e_s, erow, j0);
        __syncthreads();
        for (int j = 0; j < 32; j++) {
            float ev = e_s[j * 260 + t];
#pragma unroll
            for (int hh = 0; hh < 8; hh++)
                acc[hh] = fmaf(s_s[hh * 388 + j0 + j], ev, acc[hh]);
        }
    }
#pragma unroll
    for (int hh = 0; hh < 8; hh++) g_g[(i * kH + hh) * kD + t] = acc[hh];
}

// ---------------- K3: x_heads -> x_cat -> x_out ------------------------------
__global__ __launch_bounds__(256) void k3_xout(
    const float* __restrict__ Wv_e, const float* __restrict__ bv_e,
    const float* __restrict__ WOx,  const float* __restrict__ bOx,
    float* __restrict__ x_out)
{
    __shared__ float gs[2048];
    __shared__ float xc[256];
    int i = blockIdx.x, c = threadIdx.x;
#pragma unroll
    for (int r = 0; r < 8; r++) gs[c + r * 256] = g_g[i * 2048 + c + r * 256];
    __syncthreads();
    int h = c >> 5, k = c & 31;
    const float* wv = Wv_e + h * 8192 + k;
    const float* gh = gs + h * 256;
    float a = 0.f;
#pragma unroll 8
    for (int d = 0; d < kD; d++) a = fmaf(gh[d], wv[d * 32], a);
    xc[c] = a + bv_e[c];
    __syncthreads();
    float o = bOx[c];
#pragma unroll 8
    for (int cc = 0; cc < kD; cc++) o = fmaf(xc[cc], WOx[cc * kD + c], o);
    x_out[i * kD + c] = o;
}

// ---------------- K4: node->edge attention + output reconstruction ----------
// CTA: 4 i-rows x 96 j's. Per-j stage (floats): wj 2048 | Pj 2048 | e 4*256 | cnej 8 (+pad)
static constexpr int STAGE_F = 5136;
static constexpr int K4_SMEM = (8192 + 8192 + 2 * STAGE_F) * 4;  // 106624 B dynamic

__device__ __forceinline__ void cpa16(void* smem, const void* gmem)
{
    unsigned s = (unsigned)__cvta_generic_to_shared(smem);
    asm volatile("cp.async.ca.shared.global [%0], [%1], 16;\n" :: "r"(s), "l"(gmem));
}

__device__ __forceinline__ void k4_prefetch(float* st, const float* e, int i0, int j)
{
    const float4* wj4 = (const float4*)(w_g + (size_t)j * 2048);
    const float4* Pj4 = (const float4*)(P_g + (size_t)j * 2048);
    const float4* cn4 = (const float4*)(cne_g + j * 8);
    int t = threadIdx.x;
    for (int idx = t; idx < 1282; idx += 256) {
        if (idx < 512) {
            cpa16((float4*)st + idx, wj4 + idx);
        } else if (idx < 1024) {
            cpa16((float4*)(st + 2048) + (idx - 512), Pj4 + (idx - 512));
        } else if (idx < 1280) {
            int r = idx - 1024;
            int ii = r >> 6, off = r & 63;
            cpa16((float4*)(st + 4096) + r,
                  (const float4*)(e + (size_t)(i0 + ii) * kERow + (size_t)j * kD) + off);
        } else {
            cpa16((float4*)(st + 5120) + (idx - 1280), cn4 + (idx - 1280));
        }
    }
}

__global__ __launch_bounds__(256) void k4_ne(
    const float* __restrict__ e, const float* __restrict__ bOe,
    float* __restrict__ e_out)
{
    extern __shared__ float sm4[];
    float* wi    = sm4;          // [4][8][256]
    float* Pi    = sm4 + 8192;   // [4][8][256]
    float* stage = sm4 + 16384;  // 2 * STAGE_F
    __shared__ float bOe_s[256];
    __shared__ float cne_i[32];
    __shared__ float ai_s[32];
    __shared__ float aj_s[32];

    int t = threadIdx.x;
    int i0 = blockIdx.x * 4;
    int jbase = blockIdx.y * 96;

    for (int idx = t; idx < 8192; idx += 256) {
        wi[idx] = w_g[(size_t)i0 * 2048 + idx];
        Pi[idx] = P_g[(size_t)i0 * 2048 + idx];
    }
    bOe_s[t] = bOe[t];
    if (t < 32) cne_i[t] = cne_g[i0 * 8 + t];
    __syncthreads();

    k4_prefetch(stage, e, i0, jbase);
    asm volatile("cp.async.commit_group;\n" ::: "memory");

    int warp = t >> 5, lane = t & 31;

    for (int jj = 0; jj < 96; jj++) {
        int buf = jj & 1;
        if (jj + 1 < 96) k4_prefetch(stage + (buf ^ 1) * STAGE_F, e, i0, jbase + jj + 1);
        asm volatile("cp.async.commit_group;\n" ::: "memory");
        asm volatile("cp.async.wait_group 1;\n" ::: "memory");
        __syncthreads();

        const float* wj   = stage + buf * STAGE_F;
        const float* Pj   = wj + 2048;
        const float* est  = wj + 4096;
        const float* cnej = wj + 5120;
        int j = jbase + jj;

        // warp 'warp' == head h; compute 2-way softmax weights for 4 i-rows
        for (int ii = 0; ii < 4; ii++) {
            float si = 0.f, sj = 0.f;
#pragma unroll
            for (int r = 0; r < 8; r++) {
                int d = lane + r * 32;
                float ev = est[ii * 256 + d];
                si = fmaf(ev, wi[(ii * 8 + warp) * 256 + d], si);
                sj = fmaf(ev, wj[warp * 256 + d], sj);
            }
#pragma unroll
            for (int o = 16; o; o >>= 1) {
                si += __shfl_xor_sync(0xffffffffu, si, o);
                sj += __shfl_xor_sync(0xffffffffu, sj, o);
            }
            if (lane == 0) {
                si = (si + cne_i[ii * 8 + warp]) * kScale;
                sj = (sj + cnej[warp]) * kScale;
                float m   = fmaxf(si, sj);
                float eiv = __expf(si - m);
                float ejv = __expf(sj - m);
                float inv = 1.f / (eiv + ejv);
                ai_s[ii * 8 + warp] = eiv * inv;
                aj_s[ii * 8 + warp] = ejv * inv;
            }
        }
        __syncthreads();

        // output: thread owns column d = t, 4 rows at once (Pj reused)
        float b = bOe_s[t];
        float o0 = b, o1 = b, o2 = b, o3 = b;
#pragma unroll
        for (int hh = 0; hh < 8; hh++) {
            float pj = Pj[hh * 256 + t];
            o0 = fmaf(ai_s[hh],      Pi[hh * 256 + t],        fmaf(aj_s[hh],      pj, o0));
            o1 = fmaf(ai_s[8 + hh],  Pi[2048 + hh * 256 + t], fmaf(aj_s[8 + hh],  pj, o1));
            o2 = fmaf(ai_s[16 + hh], Pi[4096 + hh * 256 + t], fmaf(aj_s[16 + hh], pj, o2));
            o3 = fmaf(ai_s[24 + hh], Pi[6144 + hh * 256 + t], fmaf(aj_s[24 + hh], pj, o3));
        }
        float* ob = e_out + ((size_t)i0 * kN + j) * kD;
        ob[t]                      = o0;
        ob[(size_t)kERow + t]      = o1;
        ob[2 * (size_t)kERow + t]  = o2;
        ob[3 * (size_t)kERow + t]  = o3;
        __syncthreads();
    }
}

// ---------------- launch -----------------------------------------------------
extern "C" void kernel_launch(void* const* d_in, const int* in_sizes, int n_in,
                              void* d_out, int out_size)
{
    (void)in_sizes; (void)n_in; (void)out_size;
    const float* x    = (const float*)d_in[0];
    const float* e    = (const float*)d_in[1];
    const float* Wq_x = (const float*)d_in[2];
    const float* bq_x = (const float*)d_in[3];
    const float* Wk_e = (const float*)d_in[4];
    const float* bk_e = (const float*)d_in[5];
    const float* Wv_e = (const float*)d_in[6];
    const float* bv_e = (const float*)d_in[7];
    const float* Wq_e = (const float*)d_in[8];
    const float* bq_e = (const float*)d_in[9];
    const float* Wk_x = (const float*)d_in[10];
    const float* bk_x = (const float*)d_in[11];
    const float* Wv_x = (const float*)d_in[12];
    const float* bv_x = (const float*)d_in[13];
    const float* WOx  = (const float*)d_in[14];
    const float* bOx  = (const float*)d_in[15];
    const float* WOe  = (const float*)d_in[16];
    const float* bOe  = (const float*)d_in[17];

    float* out   = (float*)d_out;
    float* x_out = out;                 // [384,256]
    float* e_out = out + kN * kD;       // [384,384,256]

    cudaFuncSetAttribute(k2_en, cudaFuncAttributeMaxDynamicSharedMemorySize, K2_SMEM);
    cudaFuncSetAttribute(k4_ne, cudaFuncAttributeMaxDynamicSharedMemorySize, K4_SMEM);

    k1_proj<<<kN, 256>>>(x, Wq_x, bq_x, Wk_x, bk_x, Wv_x, bv_x, bk_e, bq_e);
    k1b_uwp<<<dim3(24, 8), 256>>>(Wk_e, Wq_e, WOe);
    k2_en<<<kN, 256, K2_SMEM>>>(e);
    k3_xout<<<kN, 256>>>(Wv_e, bv_e, WOx, bOx, x_out);
    k4_ne<<<dim3(96, 4), 256, K4_SMEM>>>(e, bOe, e_out);
}

// round 4
// speedup vs baseline: 1.0053x; 1.0053x over previous
#include <cuda_runtime.h>
#include <math.h>
#include <stdint.h>

static constexpr int kN  = 384;
static constexpr int kD  = 256;
static constexpr int kH  = 8;
static constexpr int kDH = 32;
static constexpr float kScale = 0.17677669529663687f;  // 1/sqrt(32)
static constexpr int kERow = kN * kD;                  // 98304 floats per e row i

// ---------------- scratch (__device__ globals; no allocation) ----------------
__device__ float qx_g[kN * kD];
__device__ float kx_g[kN * kD];
__device__ float vx_g[kN * kD];
__device__ float cen_g[kN * kH];      // qx . bk_e   (per i,h)
__device__ float cne_g[kN * kH];      // kx . bq_e   (per n,h)
__device__ float u_g[kN * kH * kD];   // [i][h][d]  Wk_e_h @ qx[h,i]
__device__ float w_g[kN * kH * kD];   // [n][h][d]  Wq_e_h @ kx[h,n]
__device__ float P_g[kN * kH * kD];   // [n][h][d]  vx_h[n] @ WOe rows h
__device__ float g_g[kN * kH * kD];   // [i][h][d]  sum_j a_en * e[i,j,:]

// ---------------- K1: qx/kx/vx projections + score constants ----------------
__global__ __launch_bounds__(256) void k1_proj(
    const float* __restrict__ x,
    const float* __restrict__ Wq, const float* __restrict__ bq,
    const float* __restrict__ Wk, const float* __restrict__ bk,
    const float* __restrict__ Wv, const float* __restrict__ bv,
    const float* __restrict__ bk_e, const float* __restrict__ bq_e)
{
    __shared__ float xs[kD];
    int i = blockIdx.x, c = threadIdx.x;
    xs[c] = x[i * kD + c];
    __syncthreads();
    int h = c >> 5, k = c & 31;
    const float* wq = Wq + h * 8192 + k;   // W[h,d,k] = W[h*8192 + d*32 + k]
    const float* wk = Wk + h * 8192 + k;
    const float* wv = Wv + h * 8192 + k;
    float q = 0.f, kk = 0.f, v = 0.f;
#pragma unroll 8
    for (int d = 0; d < kD; d++) {
        float xv = xs[d];
        q  = fmaf(xv, wq[d * 32], q);
        kk = fmaf(xv, wk[d * 32], kk);
        v  = fmaf(xv, wv[d * 32], v);
    }
    q += bq[c]; kk += bk[c]; v += bv[c];
    qx_g[i * kD + c] = q;
    kx_g[i * kD + c] = kk;
    vx_g[i * kD + c] = v;

    // cen[i,h] = sum_k bk_e[h,k]*qx[h,i,k];  cne[i,h] = sum_k bq_e[h,k]*kx[h,i,k]
    float ce = bk_e[c] * q;
    float cn = bq_e[c] * kk;
#pragma unroll
    for (int o = 16; o; o >>= 1) {
        ce += __shfl_xor_sync(0xffffffffu, ce, o);
        cn += __shfl_xor_sync(0xffffffffu, cn, o);
    }
    if (k == 0) { cen_g[i * kH + h] = ce; cne_g[i * kH + h] = cn; }
}

// ---------------- K1b: u / w / P tables (weights in registers, reuse x16) ----
__global__ __launch_bounds__(256) void k1b_uwp(
    const float* __restrict__ Wk_e,
    const float* __restrict__ Wq_e,
    const float* __restrict__ WOe)
{
    __shared__ float qs[16 * 32], ks[16 * 32], vs[16 * 32];
    int ib = blockIdx.x, h = blockIdx.y;
    int d = threadIdx.x;
    for (int idx = threadIdx.x; idx < 512; idx += 256) {
        int ii = idx >> 5, k = idx & 31;
        int g = (ib * 16 + ii) * kD + h * 32 + k;
        qs[idx] = qx_g[g]; ks[idx] = kx_g[g]; vs[idx] = vx_g[g];
    }
    __syncthreads();

    float wr[32];
#pragma unroll
    for (int k = 0; k < 32; k++) wr[k] = Wk_e[h * 8192 + d * 32 + k];
    for (int ii = 0; ii < 16; ii++) {
        float a = 0.f;
#pragma unroll
        for (int k = 0; k < 32; k++) a = fmaf(wr[k], qs[ii * 32 + k], a);
        u_g[((ib * 16 + ii) * kH + h) * kD + d] = a;
    }
#pragma unroll
    for (int k = 0; k < 32; k++) wr[k] = Wq_e[h * 8192 + d * 32 + k];
    for (int ii = 0; ii < 16; ii++) {
        float a = 0.f;
#pragma unroll
        for (int k = 0; k < 32; k++) a = fmaf(wr[k], ks[ii * 32 + k], a);
        w_g[((ib * 16 + ii) * kH + h) * kD + d] = a;
    }
#pragma unroll
    for (int k = 0; k < 32; k++) wr[k] = WOe[(h * 32 + k) * kD + d];
    for (int ii = 0; ii < 16; ii++) {
        float a = 0.f;
#pragma unroll
        for (int k = 0; k < 32; k++) a = fmaf(wr[k], vs[ii * 32 + k], a);
        P_g[((ib * 16 + ii) * kH + h) * kD + d] = a;
    }
}

// ---------------- K2: edge->node attention (scores, softmax, g) --------------
// smem layout (floats): u_s 8*260 | s_s 8*388 | e_s 32*260   = 13504 fl = 54016 B
static constexpr int K2_SMEM = (8 * 260 + 8 * 388 + 32 * 260) * 4;

__device__ __forceinline__ void k2_load_etile(float* e_s, const float* erow, int j0)
{
    const float4* src = (const float4*)(erow + j0 * kD);
    int t = threadIdx.x;
#pragma unroll
    for (int r = 0; r < 8; r++) {
        int idx = t + r * 256;           // float4 index, 0..2047
        int row = idx >> 6, dd = idx & 63;
        float4 v = src[idx];
        *(float4*)(e_s + row * 260 + dd * 4) = v;
    }
}

__global__ __launch_bounds__(256) void k2_en(const float* __restrict__ e)
{
    extern __shared__ float sm[];
    float* u_s = sm;            // 8*260
    float* s_s = sm + 2080;     // 8*388
    float* e_s = sm + 5184;     // 32*260
    __shared__ float cen_s[8];

    int i = blockIdx.x, t = threadIdx.x;
#pragma unroll
    for (int r = 0; r < 8; r++) {
        int idx = t + r * 256;
        int h = idx >> 8, d = idx & 255;
        u_s[h * 260 + d] = u_g[(i * kH + h) * kD + d];
    }
    if (t < 8) cen_s[t] = cen_g[i * kH + t];
    const float* erow = e + (size_t)i * kERow;

    int h = t & 7, jj = t >> 3;
    // pass A: scores for all j (s_s[h][j])
    for (int j0 = 0; j0 < kN; j0 += 32) {
        __syncthreads();
        k2_load_etile(e_s, erow, j0);
        __syncthreads();
        const float4* ev = (const float4*)(e_s + jj * 260);
        const float4* uv = (const float4*)(u_s + h * 260);
        float acc = 0.f;
#pragma unroll 16
        for (int d4 = 0; d4 < 64; d4++) {
            float4 a = ev[d4], b = uv[d4];
            acc = fmaf(a.x, b.x, acc); acc = fmaf(a.y, b.y, acc);
            acc = fmaf(a.z, b.z, acc); acc = fmaf(a.w, b.w, acc);
        }
        s_s[h * 388 + j0 + jj] = (acc + cen_s[h]) * kScale;
    }
    __syncthreads();

    // softmax per head, one warp per h
    {
        int hw = t >> 5, l = t & 31;
        float m = -1e30f;
        for (int j = l; j < kN; j += 32) m = fmaxf(m, s_s[hw * 388 + j]);
#pragma unroll
        for (int o = 16; o; o >>= 1) m = fmaxf(m, __shfl_xor_sync(0xffffffffu, m, o));
        float sum = 0.f;
        for (int j = l; j < kN; j += 32) {
            float ev = __expf(s_s[hw * 388 + j] - m);
            s_s[hw * 388 + j] = ev;
            sum += ev;
        }
#pragma unroll
        for (int o = 16; o; o >>= 1) sum += __shfl_xor_sync(0xffffffffu, sum, o);
        float inv = 1.f / sum;
        for (int j = l; j < kN; j += 32) s_s[hw * 388 + j] *= inv;
    }
    __syncthreads();

    // pass B: g[h][d] = sum_j a[h][j] * e[j][d]; thread owns column d = t
    float acc[8];
#pragma unroll
    for (int hh = 0; hh < 8; hh++) acc[hh] = 0.f;
    for (int j0 = 0; j0 < kN; j0 += 32) {
        __syncthreads();
        k2_load_etile(e_s, erow, j0);
        __syncthreads();
        for (int j = 0; j < 32; j++) {
            float ev = e_s[j * 260 + t];
#pragma unroll
            for (int hh = 0; hh < 8; hh++)
                acc[hh] = fmaf(s_s[hh * 388 + j0 + j], ev, acc[hh]);
        }
    }
#pragma unroll
    for (int hh = 0; hh < 8; hh++) g_g[(i * kH + hh) * kD + t] = acc[hh];
}

// ---------------- K3: x_heads -> x_cat -> x_out ------------------------------
__global__ __launch_bounds__(256) void k3_xout(
    const float* __restrict__ Wv_e, const float* __restrict__ bv_e,
    const float* __restrict__ WOx,  const float* __restrict__ bOx,
    float* __restrict__ x_out)
{
    __shared__ float gs[2048];
    __shared__ float xc[256];
    int i = blockIdx.x, c = threadIdx.x;
#pragma unroll
    for (int r = 0; r < 8; r++) gs[c + r * 256] = g_g[i * 2048 + c + r * 256];
    __syncthreads();
    int h = c >> 5, k = c & 31;
    const float* wv = Wv_e + h * 8192 + k;
    const float* gh = gs + h * 256;
    float a = 0.f;
#pragma unroll 8
    for (int d = 0; d < kD; d++) a = fmaf(gh[d], wv[d * 32], a);
    xc[c] = a + bv_e[c];
    __syncthreads();
    float o = bOx[c];
#pragma unroll 8
    for (int cc = 0; cc < kD; cc++) o = fmaf(xc[cc], WOx[cc * kD + c], o);
    x_out[i * kD + c] = o;
}

// ---------------- K4: node->edge attention + output reconstruction ----------
// CTA: 4 i-rows x 96 j's. Per-j stage (floats): wj 2048 | Pj 2048 | e 4*256 | cnej 8 (+pad)
static constexpr int STAGE_F = 5136;
static constexpr int K4_SMEM = (8192 + 8192 + 2 * STAGE_F) * 4;  // 106624 B dynamic

__device__ __forceinline__ void cpa16(void* smem, const void* gmem)
{
    unsigned s = (unsigned)__cvta_generic_to_shared(smem);
    asm volatile("cp.async.ca.shared.global [%0], [%1], 16;\n" :: "r"(s), "l"(gmem));
}

__device__ __forceinline__ void k4_prefetch(float* st, const float* e, int i0, int j)
{
    const float4* wj4 = (const float4*)(w_g + (size_t)j * 2048);
    const float4* Pj4 = (const float4*)(P_g + (size_t)j * 2048);
    const float4* cn4 = (const float4*)(cne_g + j * 8);
    int t = threadIdx.x;
    for (int idx = t; idx < 1282; idx += 256) {
        if (idx < 512) {
            cpa16((float4*)st + idx, wj4 + idx);
        } else if (idx < 1024) {
            cpa16((float4*)(st + 2048) + (idx - 512), Pj4 + (idx - 512));
        } else if (idx < 1280) {
            int r = idx - 1024;
            int ii = r >> 6, off = r & 63;
            cpa16((float4*)(st + 4096) + r,
                  (const float4*)(e + (size_t)(i0 + ii) * kERow + (size_t)j * kD) + off);
        } else {
            cpa16((float4*)(st + 5120) + (idx - 1280), cn4 + (idx - 1280));
        }
    }
}

__global__ __launch_bounds__(256) void k4_ne(
    const float* __restrict__ e, const float* __restrict__ bOe,
    float* __restrict__ e_out)
{
    extern __shared__ float sm4[];
    float* wi    = sm4;          // [4][8][256]
    float* Pi    = sm4 + 8192;   // [4][8][256]
    float* stage = sm4 + 16384;  // 2 * STAGE_F
    __shared__ float bOe_s[256];
    __shared__ float cne_i[32];
    __shared__ float ai_s[32];
    __shared__ float aj_s[32];

    int t = threadIdx.x;
    int i0 = blockIdx.x * 4;
    int jbase = blockIdx.y * 96;

    for (int idx = t; idx < 8192; idx += 256) {
        wi[idx] = w_g[(size_t)i0 * 2048 + idx];
        Pi[idx] = P_g[(size_t)i0 * 2048 + idx];
    }
    bOe_s[t] = bOe[t];
    if (t < 32) cne_i[t] = cne_g[i0 * 8 + t];
    __syncthreads();

    k4_prefetch(stage, e, i0, jbase);
    asm volatile("cp.async.commit_group;\n" ::: "memory");

    int warp = t >> 5, lane = t & 31;

    for (int jj = 0; jj < 96; jj++) {
        int buf = jj & 1;
        if (jj + 1 < 96) k4_prefetch(stage + (buf ^ 1) * STAGE_F, e, i0, jbase + jj + 1);
        asm volatile("cp.async.commit_group;\n" ::: "memory");
        asm volatile("cp.async.wait_group 1;\n" ::: "memory");
        __syncthreads();

        const float* wj   = stage + buf * STAGE_F;
        const float* Pj   = wj + 2048;
        const float* est  = wj + 4096;
        const float* cnej = wj + 5120;
        int j = jbase + jj;

        // warp 'warp' == head h; compute 2-way softmax weights for 4 i-rows
        for (int ii = 0; ii < 4; ii++) {
            float si = 0.f, sj = 0.f;
#pragma unroll
            for (int r = 0; r < 8; r++) {
                int d = lane + r * 32;
                float ev = est[ii * 256 + d];
                si = fmaf(ev, wi[(ii * 8 + warp) * 256 + d], si);
                sj = fmaf(ev, wj[warp * 256 + d], sj);
            }
#pragma unroll
            for (int o = 16; o; o >>= 1) {
                si += __shfl_xor_sync(0xffffffffu, si, o);
                sj += __shfl_xor_sync(0xffffffffu, sj, o);
            }
            if (lane == 0) {
                si = (si + cne_i[ii * 8 + warp]) * kScale;
                sj = (sj + cnej[warp]) * kScale;
                float m   = fmaxf(si, sj);
                float eiv = __expf(si - m);
                float ejv = __expf(sj - m);
                float inv = 1.f / (eiv + ejv);
                ai_s[ii * 8 + warp] = eiv * inv;
                aj_s[ii * 8 + warp] = ejv * inv;
            }
        }
        __syncthreads();

        // output: thread owns column d = t, 4 rows at once (Pj reused)
        float b = bOe_s[t];
        float o0 = b, o1 = b, o2 = b, o3 = b;
#pragma unroll
        for (int hh = 0; hh < 8; hh++) {
            float pj = Pj[hh * 256 + t];
            o0 = fmaf(ai_s[hh],      Pi[hh * 256 + t],        fmaf(aj_s[hh],      pj, o0));
            o1 = fmaf(ai_s[8 + hh],  Pi[2048 + hh * 256 + t], fmaf(aj_s[8 + hh],  pj, o1));
            o2 = fmaf(ai_s[16 + hh], Pi[4096 + hh * 256 + t], fmaf(aj_s[16 + hh], pj, o2));
            o3 = fmaf(ai_s[24 + hh], Pi[6144 + hh * 256 + t], fmaf(aj_s[24 + hh], pj, o3));
        }
        float* ob = e_out + ((size_t)i0 * kN + j) * kD;
        ob[t]                      = o0;
        ob[(size_t)kERow + t]      = o1;
        ob[2 * (size_t)kERow + t]  = o2;
        ob[3 * (size_t)kERow + t]  = o3;
        __syncthreads();
    }
}

// ---------------- launch -----------------------------------------------------
extern "C" void kernel_launch(void* const* d_in, const int* in_sizes, int n_in,
                              void* d_out, int out_size)
{
    (void)in_sizes; (void)n_in; (void)out_size;
    const float* x    = (const float*)d_in[0];
    const float* e    = (const float*)d_in[1];
    const float* Wq_x = (const float*)d_in[2];
    const float* bq_x = (const float*)d_in[3];
    const float* Wk_e = (const float*)d_in[4];
    const float* bk_e = (const float*)d_in[5];
    const float* Wv_e = (const float*)d_in[6];
    const float* bv_e = (const float*)d_in[7];
    const float* Wq_e = (const float*)d_in[8];
    const float* bq_e = (const float*)d_in[9];
    const float* Wk_x = (const float*)d_in[10];
    const float* bk_x = (const float*)d_in[11];
    const float* Wv_x = (const float*)d_in[12];
    const float* bv_x = (const float*)d_in[13];
    const float* WOx  = (const float*)d_in[14];
    const float* bOx  = (const float*)d_in[15];
    const float* WOe  = (const float*)d_in[16];
    const float* bOe  = (const float*)d_in[17];

    float* out   = (float*)d_out;
    float* x_out = out;                 // [384,256]
    float* e_out = out + kN * kD;       // [384,384,256]

    cudaFuncSetAttribute(k2_en, cudaFuncAttributeMaxDynamicSharedMemorySize, K2_SMEM);
    cudaFuncSetAttribute(k4_ne, cudaFuncAttributeMaxDynamicSharedMemorySize, K4_SMEM);

    k1_proj<<<kN, 256>>>(x, Wq_x, bq_x, Wk_x, bk_x, Wv_x, bv_x, bk_e, bq_e);
    k1b_uwp<<<dim3(24, 8), 256>>>(Wk_e, Wq_e, WOe);
    k2_en<<<kN, 256, K2_SMEM>>>(e);
    k3_xout<<<kN, 256>>>(Wv_e, bv_e, WOx, bOx, x_out);
    k4_ne<<<dim3(96, 4), 256, K4_SMEM>>>(e, bOe, e_out);
}

// round 5
// speedup vs baseline: 1.4178x; 1.4103x over previous
#include <cuda_runtime.h>
#include <math.h>
#include <stdint.h>

static constexpr int kN  = 384;
static constexpr int kD  = 256;
static constexpr int kH  = 8;
static constexpr float kScale = 0.17677669529663687f;  // 1/sqrt(32)
static constexpr int kERow = kN * kD;

// ---------------- scratch (__device__ globals; no allocation) ----------------
__device__ __align__(16) float qx_g[kN * kD];
__device__ __align__(16) float kx_g[kN * kD];
__device__ __align__(16) float vx_g[kN * kD];
__device__ __align__(16) float cen_g[kN * kH];          // qx . bk_e
__device__ __align__(16) float cne_g[kN * kH];          // kx . bq_e
__device__ __align__(16) float u_g[kN * kH * kD];       // [i][h][d]
__device__ __align__(16) float w_g[kN * kH * kD];       // [n][h][d]
__device__ __align__(16) float PT_g[kN * kD * 9];       // [n][d*9+h] stride-9 pad
__device__ __align__(16) float a_g[kN * kN * 16];       // [(i*N+j)*16 + h*2 + {ai,aj}]
__device__ __align__(16) float g_part_g[3 * kN * kH * kD];
__device__ __align__(16) float sum_part_g[3 * kN * kH];
__device__ __align__(16) float g_g[kN * kH * kD];

__device__ __forceinline__ void cpa16(void* smem, const void* gmem)
{
    unsigned s = (unsigned)__cvta_generic_to_shared(smem);
    asm volatile("cp.async.ca.shared.global [%0], [%1], 16;\n" :: "r"(s), "l"(gmem));
}
#define CP_COMMIT() asm volatile("cp.async.commit_group;\n" ::: "memory")
#define CP_WAIT1()  asm volatile("cp.async.wait_group 1;\n" ::: "memory")

// ---------------- K1: qx/kx/vx projections + score constants ----------------
__global__ __launch_bounds__(256) void k1_proj(
    const float* __restrict__ x,
    const float* __restrict__ Wq, const float* __restrict__ bq,
    const float* __restrict__ Wk, const float* __restrict__ bk,
    const float* __restrict__ Wv, const float* __restrict__ bv,
    const float* __restrict__ bk_e, const float* __restrict__ bq_e)
{
    __shared__ float xs[kD];
    int i = blockIdx.x, c = threadIdx.x;
    xs[c] = x[i * kD + c];
    __syncthreads();
    int h = c >> 5, k = c & 31;
    const float* wq = Wq + h * 8192 + k;   // W[h,d,k]
    const float* wk = Wk + h * 8192 + k;
    const float* wv = Wv + h * 8192 + k;
    float q = 0.f, kk = 0.f, v = 0.f;
#pragma unroll 8
    for (int d = 0; d < kD; d++) {
        float xv = xs[d];
        q  = fmaf(xv, wq[d * 32], q);
        kk = fmaf(xv, wk[d * 32], kk);
        v  = fmaf(xv, wv[d * 32], v);
    }
    q += bq[c]; kk += bk[c]; v += bv[c];
    qx_g[i * kD + c] = q;
    kx_g[i * kD + c] = kk;
    vx_g[i * kD + c] = v;

    float ce = bk_e[c] * q;
    float cn = bq_e[c] * kk;
#pragma unroll
    for (int o = 16; o; o >>= 1) {
        ce += __shfl_xor_sync(0xffffffffu, ce, o);
        cn += __shfl_xor_sync(0xffffffffu, cn, o);
    }
    if (k == 0) { cen_g[i * kH + h] = ce; cne_g[i * kH + h] = cn; }
}

// ---------------- K1b: u / w / PT tables -------------------------------------
__global__ __launch_bounds__(256) void k1b_uwp(
    const float* __restrict__ Wk_e,
    const float* __restrict__ Wq_e,
    const float* __restrict__ WOe)
{
    __shared__ float qs[16 * 32], ks[16 * 32], vs[16 * 32];
    int ib = blockIdx.x, h = blockIdx.y;
    int d = threadIdx.x;
    for (int idx = threadIdx.x; idx < 512; idx += 256) {
        int ii = idx >> 5, k = idx & 31;
        int g = (ib * 16 + ii) * kD + h * 32 + k;
        qs[idx] = qx_g[g]; ks[idx] = kx_g[g]; vs[idx] = vx_g[g];
    }
    __syncthreads();

    float wr[32];
#pragma unroll
    for (int k = 0; k < 32; k++) wr[k] = Wk_e[h * 8192 + d * 32 + k];
    for (int ii = 0; ii < 16; ii++) {
        float a = 0.f;
#pragma unroll
        for (int k = 0; k < 32; k++) a = fmaf(wr[k], qs[ii * 32 + k], a);
        u_g[((ib * 16 + ii) * kH + h) * kD + d] = a;
    }
#pragma unroll
    for (int k = 0; k < 32; k++) wr[k] = Wq_e[h * 8192 + d * 32 + k];
    for (int ii = 0; ii < 16; ii++) {
        float a = 0.f;
#pragma unroll
        for (int k = 0; k < 32; k++) a = fmaf(wr[k], ks[ii * 32 + k], a);
        w_g[((ib * 16 + ii) * kH + h) * kD + d] = a;
    }
#pragma unroll
    for (int k = 0; k < 32; k++) wr[k] = WOe[(h * 32 + k) * kD + d];
    for (int ii = 0; ii < 16; ii++) {
        float a = 0.f;
#pragma unroll
        for (int k = 0; k < 32; k++) a = fmaf(wr[k], vs[ii * 32 + k], a);
        PT_g[(size_t)(ib * 16 + ii) * 2304 + d * 9 + h] = a;
    }
}

// ---------------- K_score: fused scores + online g + a write -----------------
// 4 i-rows x 128 j per CTA, 512 threads. grid (96, 3).
__device__ __forceinline__ void ks_prefetch(float4* st, const float* e, int i0, int j)
{
    int t = threadIdx.x;
#pragma unroll
    for (int idx = t; idx < 768; idx += 512) {
        if (idx < 256) {
            int ii = idx >> 6;
            cpa16(st + idx,
                  (const float4*)(e + ((size_t)(i0 + ii) * kN + j) * kD) + (idx & 63));
        } else {
            cpa16(st + idx, (const float4*)(w_g + (size_t)j * 2048) + (idx - 256));
        }
    }
}

__global__ __launch_bounds__(512) void k_score(const float* __restrict__ e)
{
    __shared__ float4 stage4[2][768];   // [e: 256 f4][w_j: 512 f4]
    __shared__ float p_s[32];
    __shared__ float cen_s[32], cnei_s[32];

    int t = threadIdx.x;
    int i0 = blockIdx.x * 4;
    int ch = blockIdx.y;
    int jbase = ch * 128;
    int p = t >> 4, seg = t & 15;       // p: (ii,h) pair; seg: 16-wide dot segment
    int ii_s = p >> 3, h_s = p & 7;
    int d = t & 255, half = t >> 8;     // g-phase mapping

    if (t < 32) { cen_s[t] = cen_g[i0 * 8 + t]; cnei_s[t] = cne_g[i0 * 8 + t]; }

    float4 u_r[4], wi_r[4];
    {
        const float4* ub = (const float4*)u_g + ((size_t)(i0 + ii_s) * 8 + h_s) * 64;
        const float4* wb = (const float4*)w_g + ((size_t)(i0 + ii_s) * 8 + h_s) * 64;
#pragma unroll
        for (int k = 0; k < 4; k++) { u_r[k] = ub[seg + 16 * k]; wi_r[k] = wb[seg + 16 * k]; }
    }
    float g_r[16];
#pragma unroll
    for (int q = 0; q < 16; q++) g_r[q] = 0.f;
    float run_sum = 0.f;

    ks_prefetch(stage4[0], e, i0, jbase);
    CP_COMMIT();

    for (int jj = 0; jj < 128; jj++) {
        int b = jj & 1;
        if (jj + 1 < 128) ks_prefetch(stage4[b ^ 1], e, i0, jbase + jj + 1);
        CP_COMMIT();
        CP_WAIT1();
        __syncthreads();

        const float4* st4 = stage4[b];
        float acc_en = 0.f, acc_i = 0.f, acc_j = 0.f;
#pragma unroll
        for (int k = 0; k < 4; k++) {
            float4 ev = st4[ii_s * 64 + seg + 16 * k];
            float4 wj = st4[256 + h_s * 64 + seg + 16 * k];
            float4 uu = u_r[k], wi = wi_r[k];
            acc_en = fmaf(ev.x, uu.x, acc_en); acc_en = fmaf(ev.y, uu.y, acc_en);
            acc_en = fmaf(ev.z, uu.z, acc_en); acc_en = fmaf(ev.w, uu.w, acc_en);
            acc_i  = fmaf(ev.x, wi.x, acc_i);  acc_i  = fmaf(ev.y, wi.y, acc_i);
            acc_i  = fmaf(ev.z, wi.z, acc_i);  acc_i  = fmaf(ev.w, wi.w, acc_i);
            acc_j  = fmaf(ev.x, wj.x, acc_j);  acc_j  = fmaf(ev.y, wj.y, acc_j);
            acc_j  = fmaf(ev.z, wj.z, acc_j);  acc_j  = fmaf(ev.w, wj.w, acc_j);
        }
#pragma unroll
        for (int o = 1; o < 16; o <<= 1) {
            acc_en += __shfl_xor_sync(0xffffffffu, acc_en, o);
            acc_i  += __shfl_xor_sync(0xffffffffu, acc_i,  o);
            acc_j  += __shfl_xor_sync(0xffffffffu, acc_j,  o);
        }
        int j = jbase + jj;
        if (seg == 0) {
            // edge->node: no-max softmax accumulation (scores bounded, exp safe)
            float pe = __expf((acc_en + cen_s[p]) * kScale);
            run_sum += pe;
            p_s[p] = pe;
            // node->edge: 2-way softmax
            float si = (acc_i + cnei_s[p]) * kScale;
            float sj = (acc_j + cne_g[j * 8 + h_s]) * kScale;
            float ei = __expf(si), ej = __expf(sj);
            float inv = 1.f / (ei + ej);
            *(float2*)(a_g + ((size_t)(i0 + ii_s) * kN + j) * 16 + h_s * 2) =
                make_float2(ei * inv, ej * inv);
        }
        __syncthreads();

        // online g: thread owns (d, 4 heads of 'half'), all 4 rows
        const float* stf = (const float*)st4;
#pragma unroll
        for (int ii = 0; ii < 4; ii++) {
            float ed = stf[ii * 256 + d];
#pragma unroll
            for (int hh = 0; hh < 4; hh++)
                g_r[ii * 4 + hh] = fmaf(p_s[ii * 8 + half * 4 + hh], ed, g_r[ii * 4 + hh]);
        }
        __syncthreads();
    }

#pragma unroll
    for (int ii = 0; ii < 4; ii++)
#pragma unroll
        for (int hh = 0; hh < 4; hh++)
            g_part_g[(((size_t)ch * kN + i0 + ii) * 8 + half * 4 + hh) * 256 + d] =
                g_r[ii * 4 + hh];
    if (seg == 0)
        sum_part_g[((size_t)ch * kN + i0 + ii_s) * 8 + h_s] = run_sum;
}

// ---------------- K_reduce: combine 3 chunk partials + normalize -------------
__global__ __launch_bounds__(256) void k_reduce()
{
    int i = blockIdx.x, t = threadIdx.x;
#pragma unroll
    for (int h = 0; h < 8; h++) {
        float s = sum_part_g[(size_t)i * 8 + h]
                + sum_part_g[((size_t)kN + i) * 8 + h]
                + sum_part_g[((size_t)2 * kN + i) * 8 + h];
        float a = g_part_g[((size_t)i * 8 + h) * 256 + t]
                + g_part_g[(((size_t)kN + i) * 8 + h) * 256 + t]
                + g_part_g[(((size_t)2 * kN + i) * 8 + h) * 256 + t];
        g_g[((size_t)i * 8 + h) * 256 + t] = a / s;
    }
}

// ---------------- K3: x_out (2 nodes/block, 4-way ILP) -----------------------
__global__ __launch_bounds__(256) void k3_xout(
    const float* __restrict__ Wv_e, const float* __restrict__ bv_e,
    const float* __restrict__ WOx,  const float* __restrict__ bOx,
    float* __restrict__ x_out)
{
    __shared__ float gs[2][2048];
    __shared__ float xc[2][256];
    int i0 = blockIdx.x * 2, c = threadIdx.x;
#pragma unroll
    for (int r = 0; r < 8; r++) {
        gs[0][c + r * 256] = g_g[(size_t)i0 * 2048 + c + r * 256];
        gs[1][c + r * 256] = g_g[(size_t)(i0 + 1) * 2048 + c + r * 256];
    }
    __syncthreads();
    int h = c >> 5, k = c & 31;
    const float* wv = Wv_e + h * 8192 + k;
    float a00 = 0.f, a01 = 0.f, a10 = 0.f, a11 = 0.f;
#pragma unroll 4
    for (int dd = 0; dd < kD; dd += 2) {
        float w0 = wv[dd * 32], w1 = wv[(dd + 1) * 32];
        a00 = fmaf(gs[0][h * 256 + dd],     w0, a00);
        a01 = fmaf(gs[0][h * 256 + dd + 1], w1, a01);
        a10 = fmaf(gs[1][h * 256 + dd],     w0, a10);
        a11 = fmaf(gs[1][h * 256 + dd + 1], w1, a11);
    }
    xc[0][c] = a00 + a01 + bv_e[c];
    xc[1][c] = a10 + a11 + bv_e[c];
    __syncthreads();
    float o00 = bOx[c], o01 = 0.f, o10 = o00, o11 = 0.f;
#pragma unroll 4
    for (int cc = 0; cc < kD; cc += 2) {
        float w0 = WOx[cc * kD + c], w1 = WOx[(cc + 1) * kD + c];
        o00 = fmaf(xc[0][cc],     w0, o00);
        o01 = fmaf(xc[0][cc + 1], w1, o01);
        o10 = fmaf(xc[1][cc],     w0, o10);
        o11 = fmaf(xc[1][cc + 1], w1, o11);
    }
    x_out[i0 * kD + c]       = o00 + o01;
    x_out[(i0 + 1) * kD + c] = o10 + o11;
}

// ---------------- K_out: e_out from a + P tables -----------------------------
// 4 i-rows x 128 j per CTA, 512 threads. grid (96, 3).
__device__ __forceinline__ void ko_prefetch(float4* st, int i0, int j)
{
    int t = threadIdx.x;
#pragma unroll
    for (int idx = t; idx < 592; idx += 512) {
        if (idx < 576) {
            cpa16(st + idx, (const float4*)(PT_g + (size_t)j * 2304) + idx);
        } else {
            int r = idx - 576;     // 0..15 : 4 rows x 4 f4 of a
            cpa16(st + idx,
                  (const float4*)(a_g + ((size_t)(i0 + (r >> 2)) * kN + j) * 16) + (r & 3));
        }
    }
}

__global__ __launch_bounds__(512) void k_out(
    const float* __restrict__ bOe, float* __restrict__ e_out)
{
    __shared__ float4 stage4[2][592];   // [PT_j: 576 f4][a: 16 f4]
    int t = threadIdx.x, d = t & 255, half = t >> 8;
    int i0 = blockIdx.x * 4, jbase = blockIdx.y * 128;
    int r0 = half * 2, r1 = half * 2 + 1;

    float Pi0[8], Pi1[8];
#pragma unroll
    for (int h = 0; h < 8; h++) {
        Pi0[h] = PT_g[(size_t)(i0 + r0) * 2304 + d * 9 + h];
        Pi1[h] = PT_g[(size_t)(i0 + r1) * 2304 + d * 9 + h];
    }
    float bo = bOe[d];

    ko_prefetch(stage4[0], i0, jbase);
    CP_COMMIT();

    for (int jj = 0; jj < 128; jj++) {
        int b = jj & 1;
        if (jj + 1 < 128) ko_prefetch(stage4[b ^ 1], i0, jbase + jj + 1);
        CP_COMMIT();
        CP_WAIT1();
        __syncthreads();

        const float* st = (const float*)stage4[b];
        const float* av = st + 2304;
        float o0 = bo, o1 = bo;
#pragma unroll
        for (int h = 0; h < 8; h++) {
            float pj = st[d * 9 + h];
            o0 = fmaf(av[r0 * 16 + h * 2], Pi0[h], fmaf(av[r0 * 16 + h * 2 + 1], pj, o0));
            o1 = fmaf(av[r1 * 16 + h * 2], Pi1[h], fmaf(av[r1 * 16 + h * 2 + 1], pj, o1));
        }
        int j = jbase + jj;
        e_out[((size_t)(i0 + r0) * kN + j) * kD + d] = o0;
        e_out[((size_t)(i0 + r1) * kN + j) * kD + d] = o1;
        __syncthreads();
    }
}

// ---------------- launch -----------------------------------------------------
extern "C" void kernel_launch(void* const* d_in, const int* in_sizes, int n_in,
                              void* d_out, int out_size)
{
    (void)in_sizes; (void)n_in; (void)out_size;
    const float* x    = (const float*)d_in[0];
    const float* e    = (const float*)d_in[1];
    const float* Wq_x = (const float*)d_in[2];
    const float* bq_x = (const float*)d_in[3];
    const float* Wk_e = (const float*)d_in[4];
    const float* bk_e = (const float*)d_in[5];
    const float* Wv_e = (const float*)d_in[6];
    const float* bv_e = (const float*)d_in[7];
    const float* Wq_e = (const float*)d_in[8];
    const float* bq_e = (const float*)d_in[9];
    const float* Wk_x = (const float*)d_in[10];
    const float* bk_x = (const float*)d_in[11];
    const float* Wv_x = (const float*)d_in[12];
    const float* bv_x = (const float*)d_in[13];
    const float* WOx  = (const float*)d_in[14];
    const float* bOx  = (const float*)d_in[15];
    const float* WOe  = (const float*)d_in[16];
    const float* bOe  = (const float*)d_in[17];

    float* out   = (float*)d_out;
    float* x_out = out;                 // [384,256]
    float* e_out = out + kN * kD;       // [384,384,256]

    k1_proj<<<kN, 256>>>(x, Wq_x, bq_x, Wk_x, bk_x, Wv_x, bv_x, bk_e, bq_e);
    k1b_uwp<<<dim3(24, 8), 256>>>(Wk_e, Wq_e, WOe);
    k_score<<<dim3(96, 3), 512>>>(e);
    k_reduce<<<kN, 256>>>();
    k3_xout<<<kN / 2, 256>>>(Wv_e, bv_e, WOx, bOx, x_out);
    k_out<<<dim3(96, 3), 512>>>(bOe, e_out);
}

// round 6
// speedup vs baseline: 1.7044x; 1.2021x over previous
#include <cuda_runtime.h>
#include <math.h>
#include <stdint.h>

static constexpr int kN  = 384;
static constexpr int kD  = 256;
static constexpr int kH  = 8;
static constexpr float kScale = 0.17677669529663687f;  // 1/sqrt(32)

// ---------------- scratch (__device__ globals; no allocation) ----------------
__device__ __align__(16) float qx_g[kN * kD];
__device__ __align__(16) float kx_g[kN * kD];
__device__ __align__(16) float vx_g[kN * kD];
__device__ __align__(16) float cen_g[kN * kH];          // qx . bk_e
__device__ __align__(16) float cne_g[kN * kH];          // kx . bq_e
__device__ __align__(16) float u_g[kN * kH * kD];       // [i][h][d]
__device__ __align__(16) float w_g[kN * kH * kD];       // [n][h][d]
__device__ __align__(16) float PT_g[kN * kD * 9];       // [n][d*9+h] stride-9 pad
__device__ __align__(16) float g_part_g[3 * kN * kH * kD];
__device__ __align__(16) float sum_part_g[3 * kN * kH];

__device__ __forceinline__ void cpa16(void* smem, const void* gmem)
{
    unsigned s = (unsigned)__cvta_generic_to_shared(smem);
    asm volatile("cp.async.ca.shared.global [%0], [%1], 16;\n" :: "r"(s), "l"(gmem));
}
#define CP_COMMIT() asm volatile("cp.async.commit_group;\n" ::: "memory")
#define CP_WAIT0()  asm volatile("cp.async.wait_group 0;\n" ::: "memory")

// ---------------- K1: qx/kx/vx projections + score constants ----------------
__global__ __launch_bounds__(256) void k1_proj(
    const float* __restrict__ x,
    const float* __restrict__ Wq, const float* __restrict__ bq,
    const float* __restrict__ Wk, const float* __restrict__ bk,
    const float* __restrict__ Wv, const float* __restrict__ bv,
    const float* __restrict__ bk_e, const float* __restrict__ bq_e)
{
    __shared__ float xs[kD];
    int i = blockIdx.x, c = threadIdx.x;
    xs[c] = x[i * kD + c];
    __syncthreads();
    int h = c >> 5, k = c & 31;
    const float* wq = Wq + h * 8192 + k;
    const float* wk = Wk + h * 8192 + k;
    const float* wv = Wv + h * 8192 + k;
    float q = 0.f, kk = 0.f, v = 0.f;
#pragma unroll 8
    for (int d = 0; d < kD; d++) {
        float xv = xs[d];
        q  = fmaf(xv, wq[d * 32], q);
        kk = fmaf(xv, wk[d * 32], kk);
        v  = fmaf(xv, wv[d * 32], v);
    }
    q += bq[c]; kk += bk[c]; v += bv[c];
    qx_g[i * kD + c] = q;
    kx_g[i * kD + c] = kk;
    vx_g[i * kD + c] = v;

    float ce = bk_e[c] * q;
    float cn = bq_e[c] * kk;
#pragma unroll
    for (int o = 16; o; o >>= 1) {
        ce += __shfl_xor_sync(0xffffffffu, ce, o);
        cn += __shfl_xor_sync(0xffffffffu, cn, o);
    }
    if (k == 0) { cen_g[i * kH + h] = ce; cne_g[i * kH + h] = cn; }
}

// ---------------- K1b: u / w / PT tables -------------------------------------
__global__ __launch_bounds__(256) void k1b_uwp(
    const float* __restrict__ Wk_e,
    const float* __restrict__ Wq_e,
    const float* __restrict__ WOe)
{
    __shared__ float qs[16 * 32], ks[16 * 32], vs[16 * 32];
    int ib = blockIdx.x, h = blockIdx.y;
    int d = threadIdx.x;
    for (int idx = threadIdx.x; idx < 512; idx += 256) {
        int ii = idx >> 5, k = idx & 31;
        int g = (ib * 16 + ii) * kD + h * 32 + k;
        qs[idx] = qx_g[g]; ks[idx] = kx_g[g]; vs[idx] = vx_g[g];
    }
    __syncthreads();

    float wr[32];
#pragma unroll
    for (int k = 0; k < 32; k++) wr[k] = Wk_e[h * 8192 + d * 32 + k];
    for (int ii = 0; ii < 16; ii++) {
        float a = 0.f;
#pragma unroll
        for (int k = 0; k < 32; k++) a = fmaf(wr[k], qs[ii * 32 + k], a);
        u_g[((ib * 16 + ii) * kH + h) * kD + d] = a;
    }
#pragma unroll
    for (int k = 0; k < 32; k++) wr[k] = Wq_e[h * 8192 + d * 32 + k];
    for (int ii = 0; ii < 16; ii++) {
        float a = 0.f;
#pragma unroll
        for (int k = 0; k < 32; k++) a = fmaf(wr[k], ks[ii * 32 + k], a);
        w_g[((ib * 16 + ii) * kH + h) * kD + d] = a;
    }
#pragma unroll
    for (int k = 0; k < 32; k++) wr[k] = WOe[(h * 32 + k) * kD + d];
    for (int ii = 0; ii < 16; ii++) {
        float a = 0.f;
#pragma unroll
        for (int k = 0; k < 32; k++) a = fmaf(wr[k], vs[ii * 32 + k], a);
        PT_g[(size_t)(ib * 16 + ii) * 2304 + d * 9 + h] = a;
    }
}

// ---------------- K_fused: scores + both softmaxes + g + e_out ---------------
// 4 i-rows, 128 j per CTA (2 j per iteration), 512 threads, grid (96, 3).
// Stage (floats): E 2x1024 | W 2x2048 | PT 2x2304  = 10752 fl = 43008 B.
static constexpr int STG_F   = 10752;
static constexpr int STG_F4  = 2688;
static constexpr int FUSED_SMEM = 2 * STG_F * 4;   // 86016 B

__device__ __forceinline__ void kf_prefetch(float4* st, const float* e, int i0, int j0)
{
    int t = threadIdx.x;
#pragma unroll
    for (int k = 0; k < 6; k++) {              // 6*512 = 3072 >= 2688
        int idx = t + k * 512;
        if (idx >= STG_F4) break;
        if (idx < 512) {
            int jq = idx >> 8, r = idx & 255;
            int ii = r >> 6, c = r & 63;
            cpa16(st + idx,
                  (const float4*)(e) + ((size_t)(i0 + ii) * kN + (j0 + jq)) * 64 + c);
        } else if (idx < 1536) {
            int r = idx - 512;
            int jq = r >> 9, q = r & 511;
            cpa16(st + idx, (const float4*)w_g + (size_t)(j0 + jq) * 512 + q);
        } else {
            int r = idx - 1536;
            int jq = (r >= 576) ? 1 : 0;
            int q  = r - jq * 576;
            cpa16(st + idx, (const float4*)PT_g + (size_t)(j0 + jq) * 576 + q);
        }
    }
}

__global__ __launch_bounds__(512, 1) void k_fused(
    const float* __restrict__ e, const float* __restrict__ bOe,
    float* __restrict__ e_out)
{
    extern __shared__ float4 smem4[];
    float4* stage[2] = { smem4, smem4 + STG_F4 };
    __shared__ float  p_s[2][32];
    __shared__ float2 a_s[2][32];
    __shared__ float  cen_s[32], cnei_s[32];

    int t = threadIdx.x;
    int i0 = blockIdx.x * 4;
    int ch = blockIdx.y;
    int jbase = ch * 128;

    int p = t >> 4, seg = t & 15;       // score mapping: 32 (ii,h) pairs x 16 segs
    int ii_s = p >> 3, h_s = p & 7;
    int d = t & 255, half = t >> 8;     // g/out mapping
    int r0 = half * 2, r1 = half * 2 + 1;

    if (t < 32) { cen_s[t] = cen_g[i0 * 8 + t]; cnei_s[t] = cne_g[i0 * 8 + t]; }

    // loop-invariant registers
    float4 u_r[4], wi_r[4];
    {
        const float4* ub = (const float4*)u_g + ((size_t)(i0 + ii_s) * 8 + h_s) * 64;
        const float4* wb = (const float4*)w_g + ((size_t)(i0 + ii_s) * 8 + h_s) * 64;
#pragma unroll
        for (int k = 0; k < 4; k++) { u_r[k] = ub[seg + 16 * k]; wi_r[k] = wb[seg + 16 * k]; }
    }
    float Pi0[8], Pi1[8];
#pragma unroll
    for (int h = 0; h < 8; h++) {
        Pi0[h] = PT_g[(size_t)(i0 + r0) * 2304 + d * 9 + h];
        Pi1[h] = PT_g[(size_t)(i0 + r1) * 2304 + d * 9 + h];
    }
    float bo = bOe[d];
    float g_r[16];
#pragma unroll
    for (int q = 0; q < 16; q++) g_r[q] = 0.f;
    float run_sum = 0.f;

    kf_prefetch(stage[0], e, i0, jbase);
    CP_COMMIT();

    for (int it = 0; it < 64; it++) {
        int buf = it & 1;
        int j0 = jbase + it * 2;

        CP_WAIT0();
        __syncthreads();                       // stage[buf] ready; prev reads done

        if (it + 1 < 64) { kf_prefetch(stage[buf ^ 1], e, i0, j0 + 2); CP_COMMIT(); }

        // ---- score phase ----
        const float4* st4 = stage[buf];
        float acc[6];
#pragma unroll
        for (int q = 0; q < 6; q++) acc[q] = 0.f;
#pragma unroll
        for (int k = 0; k < 4; k++) {
            float4 uu = u_r[k], wi = wi_r[k];
#pragma unroll
            for (int jq = 0; jq < 2; jq++) {
                float4 ev = st4[jq * 256 + ii_s * 64 + seg + 16 * k];
                float4 wj = st4[512 + jq * 512 + h_s * 64 + seg + 16 * k];
                float* a = acc + jq * 3;
                a[0] = fmaf(ev.x, uu.x, a[0]); a[0] = fmaf(ev.y, uu.y, a[0]);
                a[0] = fmaf(ev.z, uu.z, a[0]); a[0] = fmaf(ev.w, uu.w, a[0]);
                a[1] = fmaf(ev.x, wi.x, a[1]); a[1] = fmaf(ev.y, wi.y, a[1]);
                a[1] = fmaf(ev.z, wi.z, a[1]); a[1] = fmaf(ev.w, wi.w, a[1]);
                a[2] = fmaf(ev.x, wj.x, a[2]); a[2] = fmaf(ev.y, wj.y, a[2]);
                a[2] = fmaf(ev.z, wj.z, a[2]); a[2] = fmaf(ev.w, wj.w, a[2]);
            }
        }
#pragma unroll
        for (int o = 1; o < 16; o <<= 1)
#pragma unroll
            for (int q = 0; q < 6; q++)
                acc[q] += __shfl_xor_sync(0xffffffffu, acc[q], o);

        if (seg == 0) {
#pragma unroll
            for (int jq = 0; jq < 2; jq++) {
                int j = j0 + jq;
                float pe = __expf((acc[jq * 3] + cen_s[p]) * kScale);
                run_sum += pe;
                p_s[jq][p] = pe;
                float si = (acc[jq * 3 + 1] + cnei_s[p]) * kScale;
                float sj = (acc[jq * 3 + 2] + cne_g[j * 8 + h_s]) * kScale;
                float ei = __expf(si), ej = __expf(sj);
                float inv = 1.f / (ei + ej);
                a_s[jq][p] = make_float2(ei * inv, ej * inv);
            }
        }
        __syncthreads();                       // scores visible

        // ---- g + out phase ----
        const float* stf = (const float*)st4;
        const float* ptf = stf + 6144;
#pragma unroll
        for (int jq = 0; jq < 2; jq++) {
#pragma unroll
            for (int ii = 0; ii < 4; ii++) {
                float ed = stf[jq * 1024 + ii * 256 + d];
#pragma unroll
                for (int hh = 0; hh < 4; hh++)
                    g_r[ii * 4 + hh] =
                        fmaf(p_s[jq][ii * 8 + half * 4 + hh], ed, g_r[ii * 4 + hh]);
            }
            float o0 = bo, o1 = bo;
#pragma unroll
            for (int h = 0; h < 8; h++) {
                float pj = ptf[jq * 2304 + d * 9 + h];
                float2 a0 = a_s[jq][r0 * 8 + h];
                float2 a1 = a_s[jq][r1 * 8 + h];
                o0 = fmaf(a0.x, Pi0[h], fmaf(a0.y, pj, o0));
                o1 = fmaf(a1.x, Pi1[h], fmaf(a1.y, pj, o1));
            }
            int j = j0 + jq;
            e_out[((size_t)(i0 + r0) * kN + j) * kD + d] = o0;
            e_out[((size_t)(i0 + r1) * kN + j) * kD + d] = o1;
        }
    }

#pragma unroll
    for (int ii = 0; ii < 4; ii++)
#pragma unroll
        for (int hh = 0; hh < 4; hh++)
            g_part_g[(((size_t)ch * kN + i0 + ii) * 8 + half * 4 + hh) * 256 + d] =
                g_r[ii * 4 + hh];
    if (seg == 0)
        sum_part_g[((size_t)ch * kN + i0 + ii_s) * 8 + h_s] = run_sum;
}

// ---------------- K3: fused reduce + x_out (2 nodes/block) -------------------
__global__ __launch_bounds__(256) void k3_xout(
    const float* __restrict__ Wv_e, const float* __restrict__ bv_e,
    const float* __restrict__ WOx,  const float* __restrict__ bOx,
    float* __restrict__ x_out)
{
    __shared__ float gs[2][2048];
    __shared__ float xc[2][256];
    __shared__ float inv_s[16];
    int i0 = blockIdx.x * 2, c = threadIdx.x;

    if (c < 16) {
        int r = c >> 3, h = c & 7;
        float s = sum_part_g[(size_t)(i0 + r) * 8 + h]
                + sum_part_g[((size_t)kN + i0 + r) * 8 + h]
                + sum_part_g[((size_t)2 * kN + i0 + r) * 8 + h];
        inv_s[c] = 1.f / s;
    }
    __syncthreads();
#pragma unroll
    for (int rr = 0; rr < 8; rr++) {
#pragma unroll
        for (int r = 0; r < 2; r++) {
            float a = g_part_g[((size_t)(i0 + r) * 8 + rr) * 256 + c]
                    + g_part_g[(((size_t)kN + i0 + r) * 8 + rr) * 256 + c]
                    + g_part_g[(((size_t)2 * kN + i0 + r) * 8 + rr) * 256 + c];
            gs[r][rr * 256 + c] = a * inv_s[r * 8 + rr];
        }
    }
    __syncthreads();
    int h = c >> 5, k = c & 31;
    const float* wv = Wv_e + h * 8192 + k;
    float a00 = 0.f, a01 = 0.f, a10 = 0.f, a11 = 0.f;
#pragma unroll 4
    for (int dd = 0; dd < kD; dd += 2) {
        float w0 = wv[dd * 32], w1 = wv[(dd + 1) * 32];
        a00 = fmaf(gs[0][h * 256 + dd],     w0, a00);
        a01 = fmaf(gs[0][h * 256 + dd + 1], w1, a01);
        a10 = fmaf(gs[1][h * 256 + dd],     w0, a10);
        a11 = fmaf(gs[1][h * 256 + dd + 1], w1, a11);
    }
    xc[0][c] = a00 + a01 + bv_e[c];
    xc[1][c] = a10 + a11 + bv_e[c];
    __syncthreads();
    float o00 = bOx[c], o01 = 0.f, o10 = o00, o11 = 0.f;
#pragma unroll 4
    for (int cc = 0; cc < kD; cc += 2) {
        float w0 = WOx[cc * kD + c], w1 = WOx[(cc + 1) * kD + c];
        o00 = fmaf(xc[0][cc],     w0, o00);
        o01 = fmaf(xc[0][cc + 1], w1, o01);
        o10 = fmaf(xc[1][cc],     w0, o10);
        o11 = fmaf(xc[1][cc + 1], w1, o11);
    }
    x_out[i0 * kD + c]       = o00 + o01;
    x_out[(i0 + 1) * kD + c] = o10 + o11;
}

// ---------------- launch -----------------------------------------------------
extern "C" void kernel_launch(void* const* d_in, const int* in_sizes, int n_in,
                              void* d_out, int out_size)
{
    (void)in_sizes; (void)n_in; (void)out_size;
    const float* x    = (const float*)d_in[0];
    const float* e    = (const float*)d_in[1];
    const float* Wq_x = (const float*)d_in[2];
    const float* bq_x = (const float*)d_in[3];
    const float* Wk_e = (const float*)d_in[4];
    const float* bk_e = (const float*)d_in[5];
    const float* Wv_e = (const float*)d_in[6];
    const float* bv_e = (const float*)d_in[7];
    const float* Wq_e = (const float*)d_in[8];
    const float* bq_e = (const float*)d_in[9];
    const float* Wk_x = (const float*)d_in[10];
    const float* bk_x = (const float*)d_in[11];
    const float* Wv_x = (const float*)d_in[12];
    const float* bv_x = (const float*)d_in[13];
    const float* WOx  = (const float*)d_in[14];
    const float* bOx  = (const float*)d_in[15];
    const float* WOe  = (const float*)d_in[16];
    const float* bOe  = (const float*)d_in[17];

    float* out   = (float*)d_out;
    float* x_out = out;                 // [384,256]
    float* e_out = out + kN * kD;       // [384,384,256]

    cudaFuncSetAttribute(k_fused, cudaFuncAttributeMaxDynamicSharedMemorySize, FUSED_SMEM);

    k1_proj<<<kN, 256>>>(x, Wq_x, bq_x, Wk_x, bk_x, Wv_x, bv_x, bk_e, bq_e);
    k1b_uwp<<<dim3(24, 8), 256>>>(Wk_e, Wq_e, WOe);
    k_fused<<<dim3(96, 3), 512, FUSED_SMEM>>>(e, bOe, e_out);
    k3_xout<<<kN / 2, 256>>>(Wv_e, bv_e, WOx, bOx, x_out);
}

// round 7
// speedup vs baseline: 1.9263x; 1.1302x over previous
#include <cuda_runtime.h>
#include <math.h>
#include <stdint.h>

static constexpr int kN  = 384;
static constexpr int kD  = 256;
static constexpr int kH  = 8;
static constexpr float kScale = 0.17677669529663687f;  // 1/sqrt(32)

// ---------------- scratch (__device__ globals; no allocation) ----------------
__device__ __align__(16) float qx_g[kN * kD];
__device__ __align__(16) float kx_g[kN * kD];
__device__ __align__(16) float vx_g[kN * kD];
__device__ __align__(16) float cen_g[kN * kH];          // qx . bk_e
__device__ __align__(16) float cne_g[kN * kH];          // kx . bq_e
__device__ __align__(16) float u_g[kN * kH * kD];       // [i][h][d]
__device__ __align__(16) float w_g[kN * kH * kD];       // [n][h][d]
__device__ __align__(16) float PT_g[kN * kD * 9];       // [n][d*9+h] stride-9 pad
__device__ __align__(16) float g_part_g[3 * kN * kH * kD];
__device__ __align__(16) float sum_part_g[3 * kN * kH];

__device__ __forceinline__ void cpa16(void* smem, const void* gmem)
{
    unsigned s = (unsigned)__cvta_generic_to_shared(smem);
    asm volatile("cp.async.ca.shared.global [%0], [%1], 16;\n" :: "r"(s), "l"(gmem));
}
#define CP_COMMIT() asm volatile("cp.async.commit_group;\n" ::: "memory")
#define CP_WAIT2()  asm volatile("cp.async.wait_group 2;\n" ::: "memory")

// ---------------- K1: qx/kx/vx projections + score constants ----------------
__global__ __launch_bounds__(256) void k1_proj(
    const float* __restrict__ x,
    const float* __restrict__ Wq, const float* __restrict__ bq,
    const float* __restrict__ Wk, const float* __restrict__ bk,
    const float* __restrict__ Wv, const float* __restrict__ bv,
    const float* __restrict__ bk_e, const float* __restrict__ bq_e)
{
    __shared__ float xs[kD];
    int i = blockIdx.x, c = threadIdx.x;
    xs[c] = x[i * kD + c];
    __syncthreads();
    int h = c >> 5, k = c & 31;
    const float* wq = Wq + h * 8192 + k;
    const float* wk = Wk + h * 8192 + k;
    const float* wv = Wv + h * 8192 + k;
    float q = 0.f, kk = 0.f, v = 0.f;
#pragma unroll 8
    for (int d = 0; d < kD; d++) {
        float xv = xs[d];
        q  = fmaf(xv, wq[d * 32], q);
        kk = fmaf(xv, wk[d * 32], kk);
        v  = fmaf(xv, wv[d * 32], v);
    }
    q += bq[c]; kk += bk[c]; v += bv[c];
    qx_g[i * kD + c] = q;
    kx_g[i * kD + c] = kk;
    vx_g[i * kD + c] = v;

    float ce = bk_e[c] * q;
    float cn = bq_e[c] * kk;
#pragma unroll
    for (int o = 16; o; o >>= 1) {
        ce += __shfl_xor_sync(0xffffffffu, ce, o);
        cn += __shfl_xor_sync(0xffffffffu, cn, o);
    }
    if (k == 0) { cen_g[i * kH + h] = ce; cne_g[i * kH + h] = cn; }
}

// ---------------- K1b: u / w / PT tables -------------------------------------
__global__ __launch_bounds__(256) void k1b_uwp(
    const float* __restrict__ Wk_e,
    const float* __restrict__ Wq_e,
    const float* __restrict__ WOe)
{
    __shared__ float qs[16 * 32], ks[16 * 32], vs[16 * 32];
    int ib = blockIdx.x, h = blockIdx.y;
    int d = threadIdx.x;
    for (int idx = threadIdx.x; idx < 512; idx += 256) {
        int ii = idx >> 5, k = idx & 31;
        int g = (ib * 16 + ii) * kD + h * 32 + k;
        qs[idx] = qx_g[g]; ks[idx] = kx_g[g]; vs[idx] = vx_g[g];
    }
    __syncthreads();

    float wr[32];
#pragma unroll
    for (int k = 0; k < 32; k++) wr[k] = Wk_e[h * 8192 + d * 32 + k];
    for (int ii = 0; ii < 16; ii++) {
        float a = 0.f;
#pragma unroll
        for (int k = 0; k < 32; k++) a = fmaf(wr[k], qs[ii * 32 + k], a);
        u_g[((ib * 16 + ii) * kH + h) * kD + d] = a;
    }
#pragma unroll
    for (int k = 0; k < 32; k++) wr[k] = Wq_e[h * 8192 + d * 32 + k];
    for (int ii = 0; ii < 16; ii++) {
        float a = 0.f;
#pragma unroll
        for (int k = 0; k < 32; k++) a = fmaf(wr[k], ks[ii * 32 + k], a);
        w_g[((ib * 16 + ii) * kH + h) * kD + d] = a;
    }
#pragma unroll
    for (int k = 0; k < 32; k++) wr[k] = WOe[(h * 32 + k) * kD + d];
    for (int ii = 0; ii < 16; ii++) {
        float a = 0.f;
#pragma unroll
        for (int k = 0; k < 32; k++) a = fmaf(wr[k], vs[ii * 32 + k], a);
        PT_g[(size_t)(ib * 16 + ii) * 2304 + d * 9 + h] = a;
    }
}

// ---------------- K_fused: pipelined scores/softmax/g/e_out ------------------
// 4 i-rows, 2 j per slot, 4-slot cp.async ring, 1 barrier/iter, 512 thr.
// Slot (float4): E 512 | W 1024 | PT 1152 | cne 4  = 2692 f4 = 43072 B.
static constexpr int STG_F4 = 2692;
static constexpr int FUSED_SMEM = 4 * STG_F4 * 16;   // 172288 B

__device__ __forceinline__ void kf_prefetch(float4* st, const float* e, int i0, int j0)
{
    int t = threadIdx.x;
#pragma unroll
    for (int k = 0; k < 6; k++) {
        int idx = t + k * 512;
        if (idx >= STG_F4) break;
        if (idx < 512) {
            int jq = idx >> 8, r = idx & 255;
            int ii = r >> 6, c = r & 63;
            cpa16(st + idx,
                  (const float4*)(e) + ((size_t)(i0 + ii) * kN + (j0 + jq)) * 64 + c);
        } else if (idx < 1536) {
            int r = idx - 512;
            int jq = r >> 9, q = r & 511;
            cpa16(st + idx, (const float4*)w_g + (size_t)(j0 + jq) * 512 + q);
        } else if (idx < 2688) {
            int r = idx - 1536;
            int jq = (r >= 576) ? 1 : 0;
            int q  = r - jq * 576;
            cpa16(st + idx, (const float4*)PT_g + (size_t)(j0 + jq) * 576 + q);
        } else {
            cpa16(st + idx, (const float4*)cne_g + (size_t)j0 * 2 + (idx - 2688));
        }
    }
}

__global__ __launch_bounds__(512, 1) void k_fused(
    const float* __restrict__ e, const float* __restrict__ bOe,
    float* __restrict__ e_out)
{
    extern __shared__ float4 smem4[];
    __shared__ float  p_s[2][2][32];
    __shared__ float2 a_s[2][2][32];
    __shared__ float  cen_s[32], cnei_s[32];

    int t = threadIdx.x;
    int i0 = blockIdx.x * 4;
    int ch = blockIdx.y;
    int jbase = ch * 128;

    int p = t >> 4, seg = t & 15;       // score: 32 (ii,h) pairs x 16 segs
    int ii_s = p >> 3, h_s = p & 7;
    int d = t & 255, half = t >> 8;     // g/out mapping
    int r0 = half * 2, r1 = half * 2 + 1;

    if (t < 32) { cen_s[t] = cen_g[i0 * 8 + t]; cnei_s[t] = cne_g[i0 * 8 + t]; }

    float4 u_r[4], wi_r[4];
    {
        const float4* ub = (const float4*)u_g + ((size_t)(i0 + ii_s) * 8 + h_s) * 64;
        const float4* wb = (const float4*)w_g + ((size_t)(i0 + ii_s) * 8 + h_s) * 64;
#pragma unroll
        for (int k = 0; k < 4; k++) { u_r[k] = ub[seg + 16 * k]; wi_r[k] = wb[seg + 16 * k]; }
    }
    float Pi0[8], Pi1[8];
#pragma unroll
    for (int h = 0; h < 8; h++) {
        Pi0[h] = PT_g[(size_t)(i0 + r0) * 2304 + d * 9 + h];
        Pi1[h] = PT_g[(size_t)(i0 + r1) * 2304 + d * 9 + h];
    }
    float bo = bOe[d];
    float g_r[16];
#pragma unroll
    for (int q = 0; q < 16; q++) g_r[q] = 0.f;
    float run_sum = 0.f;

    kf_prefetch(smem4,          e, i0, jbase);     CP_COMMIT();
    kf_prefetch(smem4 + STG_F4, e, i0, jbase + 2); CP_COMMIT();

    for (int it = 0; it <= 64; it++) {
        __syncthreads();   // separates score[it-1] p/a writes from out[it] reads,
                           // and all reads of slot (it+2)&3 (used at it-2,it-1)
        if (it + 2 < 64)
            kf_prefetch(smem4 + (size_t)((it + 2) & 3) * STG_F4, e, i0, jbase + (it + 2) * 2);
        CP_COMMIT();
        CP_WAIT2();        // slot it&3 data ready

        if (it < 64) {
            // ---- score phase on slot it ----
            const float4* st4 = smem4 + (size_t)(it & 3) * STG_F4;
            int buf = it & 1;
            float acc[6];
#pragma unroll
            for (int q = 0; q < 6; q++) acc[q] = 0.f;
#pragma unroll
            for (int k = 0; k < 4; k++) {
                float4 uu = u_r[k], wi = wi_r[k];
#pragma unroll
                for (int jq = 0; jq < 2; jq++) {
                    float4 ev = st4[jq * 256 + ii_s * 64 + seg + 16 * k];
                    float4 wj = st4[512 + jq * 512 + h_s * 64 + seg + 16 * k];
                    float* a = acc + jq * 3;
                    a[0] = fmaf(ev.x, uu.x, a[0]); a[0] = fmaf(ev.y, uu.y, a[0]);
                    a[0] = fmaf(ev.z, uu.z, a[0]); a[0] = fmaf(ev.w, uu.w, a[0]);
                    a[1] = fmaf(ev.x, wi.x, a[1]); a[1] = fmaf(ev.y, wi.y, a[1]);
                    a[1] = fmaf(ev.z, wi.z, a[1]); a[1] = fmaf(ev.w, wi.w, a[1]);
                    a[2] = fmaf(ev.x, wj.x, a[2]); a[2] = fmaf(ev.y, wj.y, a[2]);
                    a[2] = fmaf(ev.z, wj.z, a[2]); a[2] = fmaf(ev.w, wj.w, a[2]);
                }
            }
#pragma unroll
            for (int o = 1; o < 16; o <<= 1)
#pragma unroll
                for (int q = 0; q < 6; q++)
                    acc[q] += __shfl_xor_sync(0xffffffffu, acc[q], o);

            if ((seg & 7) == 0) {          // seg 0 -> jq 0, seg 8 -> jq 1
                int jq = seg >> 3;
                const float* cnej = (const float*)st4 + 10768 + jq * 8;  // 2692*4-16+... = cne at f4 2688 -> float 10752
                float pe = __expf((acc[jq * 3] + cen_s[p]) * kScale);
                run_sum += pe;
                p_s[buf][jq][p] = pe;
                float si = (acc[jq * 3 + 1] + cnei_s[p]) * kScale;
                float sj = (acc[jq * 3 + 2] + ((const float*)st4)[10752 + jq * 8 + h_s]) * kScale;
                float ei = __expf(si), ej = __expf(sj);
                float inv = 1.f / (ei + ej);
                a_s[buf][jq][p] = make_float2(ei * inv, ej * inv);
                (void)cnej;
            }
        }

        if (it > 0) {
            // ---- g + out phase on slot it-1 ----
            const float* stf = (const float*)(smem4 + (size_t)((it - 1) & 3) * STG_F4);
            const float* ptf = stf + 6144;
            int bprev = (it - 1) & 1;
            int j0 = jbase + (it - 1) * 2;
#pragma unroll
            for (int jq = 0; jq < 2; jq++) {
#pragma unroll
                for (int ii = 0; ii < 4; ii++) {
                    float ed = stf[jq * 1024 + ii * 256 + d];
#pragma unroll
                    for (int hh = 0; hh < 4; hh++)
                        g_r[ii * 4 + hh] =
                            fmaf(p_s[bprev][jq][ii * 8 + half * 4 + hh], ed, g_r[ii * 4 + hh]);
                }
                float o0 = bo, o1 = bo;
#pragma unroll
                for (int h = 0; h < 8; h++) {
                    float pj = ptf[jq * 2304 + d * 9 + h];
                    float2 a0 = a_s[bprev][jq][r0 * 8 + h];
                    float2 a1 = a_s[bprev][jq][r1 * 8 + h];
                    o0 = fmaf(a0.x, Pi0[h], fmaf(a0.y, pj, o0));
                    o1 = fmaf(a1.x, Pi1[h], fmaf(a1.y, pj, o1));
                }
                int j = j0 + jq;
                e_out[((size_t)(i0 + r0) * kN + j) * kD + d] = o0;
                e_out[((size_t)(i0 + r1) * kN + j) * kD + d] = o1;
            }
        }
    }

    // combine jq0/jq1 run_sum partials (seg0 holds jq0, seg8 holds jq1)
    run_sum += __shfl_xor_sync(0xffffffffu, run_sum, 8);

#pragma unroll
    for (int ii = 0; ii < 4; ii++)
#pragma unroll
        for (int hh = 0; hh < 4; hh++)
            g_part_g[(((size_t)ch * kN + i0 + ii) * 8 + half * 4 + hh) * 256 + d] =
                g_r[ii * 4 + hh];
    if (seg == 0)
        sum_part_g[((size_t)ch * kN + i0 + ii_s) * 8 + h_s] = run_sum;
}

// ---------------- K3: reduce + x_out, split-d for parallelism ----------------
__global__ __launch_bounds__(512) void k3_xout(
    const float* __restrict__ Wv_e, const float* __restrict__ bv_e,
    const float* __restrict__ WOx,  const float* __restrict__ bOx,
    float* __restrict__ x_out)
{
    __shared__ float gs[2048];
    __shared__ float xc[256];
    __shared__ float part[512];
    __shared__ float inv_s[8];
    int i = blockIdx.x, t = threadIdx.x;
    int c = t & 255, pr = t >> 8;

    if (t < 8) {
        float s = sum_part_g[(size_t)i * 8 + t]
                + sum_part_g[((size_t)kN + i) * 8 + t]
                + sum_part_g[((size_t)2 * kN + i) * 8 + t];
        inv_s[t] = 1.f / s;
    }
    __syncthreads();
#pragma unroll
    for (int r = 0; r < 4; r++) {
        int idx = t + r * 512;
        int h = idx >> 8;
        float a = g_part_g[((size_t)i * 8 + h) * 256 + (idx & 255)]
                + g_part_g[(((size_t)kN + i) * 8 + h) * 256 + (idx & 255)]
                + g_part_g[(((size_t)2 * kN + i) * 8 + h) * 256 + (idx & 255)];
        gs[idx] = a * inv_s[h];
    }
    __syncthreads();

    // GEMV1: xc[c] = gs[h,:] . Wv_e[h,:,k], split over d halves
    {
        int h = c >> 5, k = c & 31;
        const float* wv = Wv_e + h * 8192 + k;
        const float* gh = gs + h * 256;
        float a0 = 0.f, a1 = 0.f;
        int dbeg = pr * 128;
#pragma unroll 4
        for (int dd = dbeg; dd < dbeg + 128; dd += 2) {
            a0 = fmaf(gh[dd],     wv[dd * 32],       a0);
            a1 = fmaf(gh[dd + 1], wv[(dd + 1) * 32], a1);
        }
        part[t] = a0 + a1;
    }
    __syncthreads();
    if (t < 256) xc[t] = part[t] + part[t + 256] + bv_e[t];
    __syncthreads();

    // GEMV2: x_out[c] = xc . WOx[:,c], split over cc halves
    {
        float o0 = 0.f, o1 = 0.f;
        int cbeg = pr * 128;
#pragma unroll 4
        for (int cc = cbeg; cc < cbeg + 128; cc += 2) {
            o0 = fmaf(xc[cc],     WOx[cc * kD + c],       o0);
            o1 = fmaf(xc[cc + 1], WOx[(cc + 1) * kD + c], o1);
        }
        part[t] = o0 + o1;
    }
    __syncthreads();
    if (t < 256) x_out[(size_t)i * kD + t] = part[t] + part[t + 256] + bOx[t];
}

// ---------------- launch -----------------------------------------------------
extern "C" void kernel_launch(void* const* d_in, const int* in_sizes, int n_in,
                              void* d_out, int out_size)
{
    (void)in_sizes; (void)n_in; (void)out_size;
    const float* x    = (const float*)d_in[0];
    const float* e    = (const float*)d_in[1];
    const float* Wq_x = (const float*)d_in[2];
    const float* bq_x = (const float*)d_in[3];
    const float* Wk_e = (const float*)d_in[4];
    const float* bk_e = (const float*)d_in[5];
    const float* Wv_e = (const float*)d_in[6];
    const float* bv_e = (const float*)d_in[7];
    const float* Wq_e = (const float*)d_in[8];
    const float* bq_e = (const float*)d_in[9];
    const float* Wk_x = (const float*)d_in[10];
    const float* bk_x = (const float*)d_in[11];
    const float* Wv_x = (const float*)d_in[12];
    const float* bv_x = (const float*)d_in[13];
    const float* WOx  = (const float*)d_in[14];
    const float* bOx  = (const float*)d_in[15];
    const float* WOe  = (const float*)d_in[16];
    const float* bOe  = (const float*)d_in[17];

    float* out   = (float*)d_out;
    float* x_out = out;                 // [384,256]
    float* e_out = out + kN * kD;       // [384,384,256]

    cudaFuncSetAttribute(k_fused, cudaFuncAttributeMaxDynamicSharedMemorySize, FUSED_SMEM);

    k1_proj<<<kN, 256>>>(x, Wq_x, bq_x, Wk_x, bk_x, Wv_x, bv_x, bk_e, bq_e);
    k1b_uwp<<<dim3(24, 8), 256>>>(Wk_e, Wq_e, WOe);
    k_fused<<<dim3(96, 3), 512, FUSED_SMEM>>>(e, bOe, e_out);
    k3_xout<<<kN, 512>>>(Wv_e, bv_e, WOx, bOx, x_out);
}